// round 7
// baseline (speedup 1.0000x reference)
#include <cuda_runtime.h>

#define NC   21
#define NC2  (NC * NC)
#define NB   8
#define HW   (512 * 512)
#define Q    (HW / 4)            // float4 groups per channel plane (65536)
#define NBLOCKS ((NB * Q) / 256) // 2048
#define D    4                   // cp.async pipeline depth (channels)

// Scratch: per-sample confusion matrices conf[b][true][pred].
// Zero at module load; the last block of each invocation re-zeroes after use.
__device__ int g_conf[NB * NC2];
__device__ unsigned int g_done;   // zero-init; reset by last block each run

__device__ __forceinline__ void cp16(unsigned smem, const void* gmem) {
    asm volatile("cp.async.cg.shared.global [%0], [%1], 16;"
                 :: "r"(smem), "l"(gmem) : "memory");
}
__device__ __forceinline__ void cp_commit() {
    asm volatile("cp.async.commit_group;" ::: "memory");
}
// n is a compile-time constant after full unroll; dead branches fold.
__device__ __forceinline__ void cp_wait_n(int n) {
    switch (n) {
        case 0: asm volatile("cp.async.wait_group 0;" ::: "memory"); break;
        case 1: asm volatile("cp.async.wait_group 1;" ::: "memory"); break;
        case 2: asm volatile("cp.async.wait_group 2;" ::: "memory"); break;
        default: asm volatile("cp.async.wait_group 3;" ::: "memory"); break;
    }
}

__global__ void __launch_bounds__(256)
conf_kernel(const float* __restrict__ pred,
            const float* __restrict__ tgt,
            float* __restrict__ out) {
    __shared__ int sconf[NC2];
    __shared__ float4 bufP[D][256];
    __shared__ float4 bufT[D][256];
    for (int i = threadIdx.x; i < NC2; i += blockDim.x) sconf[i] = 0;
    __syncthreads();

    int tid = blockIdx.x * blockDim.x + threadIdx.x;  // < NB*Q
    int b = tid >> 16;            // Q = 65536; uniform within a block
    int p = tid & (Q - 1);

    const float4* pp = reinterpret_cast<const float4*>(pred) + (size_t)b * NC * Q + p;
    const float4* tp = reinterpret_cast<const float4*>(tgt)  + (size_t)b * NC * Q + p;

    unsigned spP = (unsigned)__cvta_generic_to_shared(&bufP[0][threadIdx.x]);
    unsigned spT = (unsigned)__cvta_generic_to_shared(&bufT[0][threadIdx.x]);
    const unsigned STRIDE = 256 * sizeof(float4);     // 4096 B per ring slot

    // Prologue: channels 0..D-1 in flight (one commit group per channel)
    #pragma unroll
    for (int s = 0; s < D; s++) {
        cp16(spP + s * STRIDE, pp + (size_t)s * Q);
        cp16(spT + s * STRIDE, tp + (size_t)s * Q);
        cp_commit();
    }

    float4 pm, tm;
    int pax = 0, pay = 0, paz = 0, paw = 0;
    int tax = 0, tay = 0, taz = 0, taw = 0;

    #pragma unroll
    for (int c = 0; c < NC; c++) {
        // Allowed-pending = min(D-1, NC-1-c) ensures channel c is complete.
        cp_wait_n((NC - 1 - c) < (D - 1) ? (NC - 1 - c) : (D - 1));
        float4 v = bufP[c % D][threadIdx.x];
        float4 w = bufT[c % D][threadIdx.x];

        // Prefetch channel c+D into the slot just consumed (self-produced,
        // self-consumed: per-thread ordering makes this race-free).
        if (c + D < NC) {
            cp16(spP + (c % D) * STRIDE, pp + (size_t)(c + D) * Q);
            cp16(spT + (c % D) * STRIDE, tp + (size_t)(c + D) * Q);
            cp_commit();
        }

        if (c == 0) { pm = v; tm = w; }
        else {
            if (v.x > pm.x) { pm.x = v.x; pax = c; }
            if (v.y > pm.y) { pm.y = v.y; pay = c; }
            if (v.z > pm.z) { pm.z = v.z; paz = c; }
            if (v.w > pm.w) { pm.w = v.w; paw = c; }
            if (w.x > tm.x) { tm.x = w.x; tax = c; }
            if (w.y > tm.y) { tm.y = w.y; tay = c; }
            if (w.z > tm.z) { tm.z = w.z; taz = c; }
            if (w.w > tm.w) { tm.w = w.w; taw = c; }
        }
    }

    atomicAdd(&sconf[tax * NC + pax], 1);
    atomicAdd(&sconf[tay * NC + pay], 1);
    atomicAdd(&sconf[taz * NC + paz], 1);
    atomicAdd(&sconf[taw * NC + paw], 1);

    __syncthreads();
    for (int i = threadIdx.x; i < NC2; i += blockDim.x) {
        int v = sconf[i];
        if (v) atomicAdd(&g_conf[b * NC2 + i], v);
    }

    // ---- last-block finalize ----
    __threadfence();
    __shared__ unsigned int s_rank;
    if (threadIdx.x == 0) s_rank = atomicAdd(&g_done, 1u);
    __syncthreads();
    if (s_rank != NBLOCKS - 1) return;

    __shared__ float iou_sum[NB];
    __shared__ int   valid_cnt[NB];
    int t = threadIdx.x;
    if (t < NB) { iou_sum[t] = 0.0f; valid_cnt[t] = 0; }
    if (t == 0) g_done = 0;                 // reset for next invocation
    __syncthreads();

    if (t < NB * NC) {
        int bb = t / NC;
        int c  = t - bb * NC;
        const int* cb = &g_conf[bb * NC2];
        int tpv = __ldcg(&cb[c * NC + c]);
        int row = 0, col = 0;
        #pragma unroll
        for (int k = 0; k < NC; k++) {
            row += __ldcg(&cb[c * NC + k]);   // TP + FN
            col += __ldcg(&cb[k * NC + c]);   // TP + FP
        }
        if (tpv > 0) {
            float iou = (float)tpv / (float)(row + col - tpv);
            atomicAdd(&iou_sum[bb], iou);
            atomicAdd(&valid_cnt[bb], 1);
        }
    }
    __syncthreads();

    // Re-zero scratch for the next invocation (all reads done above).
    for (int i = t; i < NB * NC2; i += blockDim.x) g_conf[i] = 0;

    if (t == 0) {
        float s = 0.0f;
        #pragma unroll
        for (int bb = 0; bb < NB; bb++)
            s += iou_sum[bb] / fmaxf((float)valid_cnt[bb], 1.0f);
        out[0] = s / (float)NB;
    }
}

extern "C" void kernel_launch(void* const* d_in, const int* in_sizes, int n_in,
                              void* d_out, int out_size) {
    const float* pred = (const float*)d_in[0];
    const float* tgt  = (const float*)d_in[1];
    float* out = (float*)d_out;

    conf_kernel<<<NBLOCKS, 256>>>(pred, tgt, out);
}

// round 9
// speedup vs baseline: 1.2734x; 1.2734x over previous
#include <cuda_runtime.h>

#define NC   21
#define NC2  (NC * NC)
#define NB   8
#define HW   (512 * 512)
#define Q    (HW / 4)            // float4 groups per channel plane (65536)
#define TPB  512
#define NBLOCKS ((NB * Q) / TPB) // 1024

// Scratch: per-sample confusion matrices conf[b][true][pred].
// Zero at module load; the last block of each invocation re-zeroes after use.
__device__ int g_conf[NB * NC2];
__device__ unsigned int g_done;   // zero-init; reset by last block each run

__global__ void conf_kernel(const float* __restrict__ pred,
                            const float* __restrict__ tgt,
                            float* __restrict__ out) {
    __shared__ int sconf[NC2];
    for (int i = threadIdx.x; i < NC2; i += blockDim.x) sconf[i] = 0;
    __syncthreads();

    int tid = blockIdx.x * TPB + threadIdx.x;   // < NB*Q = 524288
    int b = tid >> 16;            // Q = 65536; uniform within a block
    int p = tid & (Q - 1);

    const float4* pp = reinterpret_cast<const float4*>(pred) + (size_t)b * NC * Q + p;
    const float4* tp = reinterpret_cast<const float4*>(tgt)  + (size_t)b * NC * Q + p;

    float4 pm = __ldcs(pp);
    float4 tm = __ldcs(tp);
    int pax = 0, pay = 0, paz = 0, paw = 0;
    int tax = 0, tay = 0, taz = 0, taw = 0;

    #pragma unroll
    for (int c = 1; c < NC; c++) {
        float4 v = __ldcs(pp + (size_t)c * Q);
        float4 w = __ldcs(tp + (size_t)c * Q);
        if (v.x > pm.x) { pm.x = v.x; pax = c; }
        if (v.y > pm.y) { pm.y = v.y; pay = c; }
        if (v.z > pm.z) { pm.z = v.z; paz = c; }
        if (v.w > pm.w) { pm.w = v.w; paw = c; }
        if (w.x > tm.x) { tm.x = w.x; tax = c; }
        if (w.y > tm.y) { tm.y = w.y; tay = c; }
        if (w.z > tm.z) { tm.z = w.z; taz = c; }
        if (w.w > tm.w) { tm.w = w.w; taw = c; }
    }

    atomicAdd(&sconf[tax * NC + pax], 1);
    atomicAdd(&sconf[tay * NC + pay], 1);
    atomicAdd(&sconf[taz * NC + paz], 1);
    atomicAdd(&sconf[taw * NC + paw], 1);

    __syncthreads();
    for (int i = threadIdx.x; i < NC2; i += blockDim.x) {
        int v = sconf[i];
        if (v) atomicAdd(&g_conf[b * NC2 + i], v);
    }

    // ---- last-block finalize ----
    __threadfence();
    __shared__ unsigned int s_rank;
    if (threadIdx.x == 0) s_rank = atomicAdd(&g_done, 1u);
    __syncthreads();
    if (s_rank != NBLOCKS - 1) return;

    __shared__ float iou_sum[NB];
    __shared__ int   valid_cnt[NB];
    int t = threadIdx.x;
    if (t < NB) { iou_sum[t] = 0.0f; valid_cnt[t] = 0; }
    if (t == 0) g_done = 0;                 // reset for next invocation
    __syncthreads();

    if (t < NB * NC) {
        int bb = t / NC;
        int c  = t - bb * NC;
        const int* cb = &g_conf[bb * NC2];
        int tpv = __ldcg(&cb[c * NC + c]);
        int row = 0, col = 0;
        #pragma unroll
        for (int k = 0; k < NC; k++) {
            row += __ldcg(&cb[c * NC + k]);   // TP + FN
            col += __ldcg(&cb[k * NC + c]);   // TP + FP
        }
        if (tpv > 0) {
            float iou = (float)tpv / (float)(row + col - tpv);
            atomicAdd(&iou_sum[bb], iou);
            atomicAdd(&valid_cnt[bb], 1);
        }
    }
    __syncthreads();

    // Re-zero scratch for the next invocation (all reads done above).
    for (int i = t; i < NB * NC2; i += blockDim.x) g_conf[i] = 0;

    if (t == 0) {
        float s = 0.0f;
        #pragma unroll
        for (int bb = 0; bb < NB; bb++)
            s += iou_sum[bb] / fmaxf((float)valid_cnt[bb], 1.0f);
        out[0] = s / (float)NB;
    }
}

extern "C" void kernel_launch(void* const* d_in, const int* in_sizes, int n_in,
                              void* d_out, int out_size) {
    const float* pred = (const float*)d_in[0];
    const float* tgt  = (const float*)d_in[1];
    float* out = (float*)d_out;

    conf_kernel<<<NBLOCKS, TPB>>>(pred, tgt, out);
}

// round 10
// speedup vs baseline: 1.2925x; 1.0150x over previous
#include <cuda_runtime.h>

#define NC   21
#define NC2  (NC * NC)
#define NB   8
#define HW   (512 * 512)
#define Q    (HW / 4)            // float4 groups per channel plane (65536)
#define TPB  1024
#define NBLOCKS ((NB * Q) / TPB) // 512

// Scratch: per-sample confusion matrices conf[b][true][pred].
// Zero at module load; the last block of each invocation re-zeroes after use.
__device__ int g_conf[NB * NC2];
__device__ unsigned int g_done;   // zero-init; reset by last block each run

__global__ void __launch_bounds__(TPB)
conf_kernel(const float* __restrict__ pred,
            const float* __restrict__ tgt,
            float* __restrict__ out) {
    __shared__ int sconf[NC2];
    for (int i = threadIdx.x; i < NC2; i += blockDim.x) sconf[i] = 0;
    __syncthreads();

    int tid = blockIdx.x * TPB + threadIdx.x;   // < NB*Q = 524288
    int b = tid >> 16;            // Q = 65536; uniform within a block
    int p = tid & (Q - 1);

    const float4* pp = reinterpret_cast<const float4*>(pred) + (size_t)b * NC * Q + p;
    const float4* tp = reinterpret_cast<const float4*>(tgt)  + (size_t)b * NC * Q + p;

    float4 pm = __ldcs(pp);
    float4 tm = __ldcs(tp);
    int pax = 0, pay = 0, paz = 0, paw = 0;
    int tax = 0, tay = 0, taz = 0, taw = 0;

    #pragma unroll
    for (int c = 1; c < NC; c++) {
        float4 v = __ldcs(pp + (size_t)c * Q);
        float4 w = __ldcs(tp + (size_t)c * Q);
        if (v.x > pm.x) { pm.x = v.x; pax = c; }
        if (v.y > pm.y) { pm.y = v.y; pay = c; }
        if (v.z > pm.z) { pm.z = v.z; paz = c; }
        if (v.w > pm.w) { pm.w = v.w; paw = c; }
        if (w.x > tm.x) { tm.x = w.x; tax = c; }
        if (w.y > tm.y) { tm.y = w.y; tay = c; }
        if (w.z > tm.z) { tm.z = w.z; taz = c; }
        if (w.w > tm.w) { tm.w = w.w; taw = c; }
    }

    atomicAdd(&sconf[tax * NC + pax], 1);
    atomicAdd(&sconf[tay * NC + pay], 1);
    atomicAdd(&sconf[taz * NC + paz], 1);
    atomicAdd(&sconf[taw * NC + paw], 1);

    __syncthreads();
    for (int i = threadIdx.x; i < NC2; i += blockDim.x) {
        int v = sconf[i];
        if (v) atomicAdd(&g_conf[b * NC2 + i], v);
    }

    // ---- last-block finalize ----
    __threadfence();
    __shared__ unsigned int s_rank;
    if (threadIdx.x == 0) s_rank = atomicAdd(&g_done, 1u);
    __syncthreads();
    if (s_rank != NBLOCKS - 1) return;

    __shared__ float iou_sum[NB];
    __shared__ int   valid_cnt[NB];
    int t = threadIdx.x;
    if (t < NB) { iou_sum[t] = 0.0f; valid_cnt[t] = 0; }
    if (t == 0) g_done = 0;                 // reset for next invocation
    __syncthreads();

    if (t < NB * NC) {
        int bb = t / NC;
        int c  = t - bb * NC;
        const int* cb = &g_conf[bb * NC2];
        int tpv = __ldcg(&cb[c * NC + c]);
        int row = 0, col = 0;
        #pragma unroll
        for (int k = 0; k < NC; k++) {
            row += __ldcg(&cb[c * NC + k]);   // TP + FN
            col += __ldcg(&cb[k * NC + c]);   // TP + FP
        }
        if (tpv > 0) {
            float iou = (float)tpv / (float)(row + col - tpv);
            atomicAdd(&iou_sum[bb], iou);
            atomicAdd(&valid_cnt[bb], 1);
        }
    }
    __syncthreads();

    // Re-zero scratch for the next invocation (all reads done above).
    for (int i = t; i < NB * NC2; i += blockDim.x) g_conf[i] = 0;

    if (t == 0) {
        float s = 0.0f;
        #pragma unroll
        for (int bb = 0; bb < NB; bb++)
            s += iou_sum[bb] / fmaxf((float)valid_cnt[bb], 1.0f);
        out[0] = s / (float)NB;
    }
}

extern "C" void kernel_launch(void* const* d_in, const int* in_sizes, int n_in,
                              void* d_out, int out_size) {
    const float* pred = (const float*)d_in[0];
    const float* tgt  = (const float*)d_in[1];
    float* out = (float*)d_out;

    conf_kernel<<<NBLOCKS, TPB>>>(pred, tgt, out);
}